// round 17
// baseline (speedup 1.0000x reference)
#include <cuda_runtime.h>
#include <cuda_bf16.h>
#include <cstdint>

#define BB 32
#define SS 4096
#define CC 768
#define HH 12
#define DD 64
#define NCHUNK 32
#define SCHUNK 128
#define NSLICE 8          // 8 slices of 96 columns

// ---- scratch (device globals; allocation is forbidden) ----
__device__ float g_qhp[4 * HH * DD];                          // qh partials (4 c-slices)
__device__ __nv_bfloat16 g_wkh[16 * CC];                      // folded key weights, bf16 hi (rows 12-15 zero)
__device__ __nv_bfloat16 g_wkl[16 * CC];                      // folded key weights, bf16 lo
__device__ float g_sbias[HH];                                 // qh . bk
__device__ float g_z[BB * NCHUNK * HH];                       // per-chunk expsum
__device__ float g_ypart[(size_t)BB * NCHUNK * HH * CC];      // per-chunk partial y
__device__ float g_ctx[BB * CC];                              // context (h,d flattened)

// ================= warp-mma helpers (sm_80 PTX; compiles on plain sm_103) ==========
__device__ __forceinline__ uint32_t smem_u32(const void* p) {
    uint32_t a;
    asm("{ .reg .u64 t; cvta.to.shared.u64 t, %1; cvt.u32.u64 %0, t; }" : "=r"(a) : "l"(p));
    return a;
}
__device__ __forceinline__ void ldm_x4(uint32_t* r, uint32_t addr) {
    asm volatile("ldmatrix.sync.aligned.m8n8.x4.shared.b16 {%0,%1,%2,%3}, [%4];"
        : "=r"(r[0]), "=r"(r[1]), "=r"(r[2]), "=r"(r[3]) : "r"(addr));
}
__device__ __forceinline__ void ldm_x4t(uint32_t* r, uint32_t addr) {
    asm volatile("ldmatrix.sync.aligned.m8n8.x4.trans.shared.b16 {%0,%1,%2,%3}, [%4];"
        : "=r"(r[0]), "=r"(r[1]), "=r"(r[2]), "=r"(r[3]) : "r"(addr));
}
__device__ __forceinline__ void mma16816(float* d, const uint32_t* a, const uint32_t* b) {
    asm volatile("mma.sync.aligned.m16n8k16.row.col.f32.bf16.bf16.f32 "
        "{%0,%1,%2,%3}, {%4,%5,%6,%7}, {%8,%9}, {%0,%1,%2,%3};"
        : "+f"(d[0]), "+f"(d[1]), "+f"(d[2]), "+f"(d[3])
        : "r"(a[0]), "r"(a[1]), "r"(a[2]), "r"(a[3]), "r"(b[0]), "r"(b[1]));
}
__device__ __forceinline__ uint32_t pbf2(float a, float b) {
    __nv_bfloat162 h = __floats2bfloat162_rn(a, b);
    return *reinterpret_cast<uint32_t*>(&h);
}

// ---- smem layout (bytes). X/WK row stride 208 = 13*16 (8-row ldmatrix groups
// land on distinct banks: step 52 lanes-of-4B mod 32 = 20). P stride 272.
#define XSTR  208u
#define PSTR  272u
#define OFF_XH   0u
#define OFF_XL   26624u
#define OFF_WKH  53248u
#define OFF_WKL  56576u
#define OFF_PH   59904u
#define OFF_PL   64256u
#define OFF_SBS  68608u
#define OFF_ZSH  68672u
#define SMEM_TOTAL 68736

// ================= prep 1: qh partials over 4 c-slices =================
__global__ __launch_bounds__(256) void k_prep_qh(const float* __restrict__ probe,
                                                 const float* __restrict__ Wq) {
    int h = blockIdx.x, cs = blockIdx.y, t = threadIdx.x;
    __shared__ float red[4][DD];
    int d = t & 63, part = t >> 6;
    int c0 = cs * 192;
    float a = 0.f;
    #pragma unroll 8
    for (int c = c0 + part; c < c0 + 192; c += 4)
        a = fmaf(probe[c], Wq[(size_t)c * CC + h * DD + d], a);
    red[part][d] = a;
    __syncthreads();
    if (t < DD)
        g_qhp[cs * HH * DD + h * DD + t] = red[0][t] + red[1][t] + red[2][t] + red[3][t];
}

// ================= prep 2: wk = fold(Wk,qh) -> bf16 hi/lo (rows 12-15 zeroed) ==========
__global__ __launch_bounds__(256) void k_prep_wk(const float* __restrict__ Wk,
                                                 const float* __restrict__ bq) {
    int h = blockIdx.x, sl = blockIdx.y, t = threadIdx.x;
    __shared__ float qs[DD];
    if (t < DD) {
        int i = h * DD + t;
        qs[t] = (g_qhp[i] + g_qhp[HH * DD + i] + g_qhp[2 * HH * DD + i]
               + g_qhp[3 * HH * DD + i] + bq[i]) * 0.125f;
    }
    __syncthreads();
    int base = sl * 96;
    for (int c = base + t; c < base + 96; c += 256) {
        const float4* wr = (const float4*)(Wk + (size_t)c * CC + h * DD);
        float s = 0.f;
        #pragma unroll
        for (int j = 0; j < DD / 4; j++) {
            float4 wv = wr[j];
            const float4 qv = *(const float4*)(qs + 4 * j);
            s += wv.x * qv.x + wv.y * qv.y + wv.z * qv.z + wv.w * qv.w;
        }
        __nv_bfloat16 hb = __float2bfloat16(s);
        g_wkh[h * CC + c] = hb;
        g_wkl[h * CC + c] = __float2bfloat16(s - __bfloat162float(hb));
        if (h < 4) {   // zero pad rows 12..15
            g_wkh[(HH + h) * CC + c] = __float2bfloat16(0.f);
            g_wkl[(HH + h) * CC + c] = __float2bfloat16(0.f);
        }
    }
}

// ================= prep 3: sbias[h] = qh[h,:].bk[h,:] =================
__global__ __launch_bounds__(384) void k_prep_sb(const float* __restrict__ bq,
                                                 const float* __restrict__ bk) {
    int t = threadIdx.x, h = t >> 5, lane = t & 31;
    int i1 = h * DD + lane, i2 = i1 + 32;
    float q1 = (g_qhp[i1] + g_qhp[HH * DD + i1] + g_qhp[2 * HH * DD + i1]
              + g_qhp[3 * HH * DD + i1] + bq[i1]) * 0.125f;
    float q2 = (g_qhp[i2] + g_qhp[HH * DD + i2] + g_qhp[2 * HH * DD + i2]
              + g_qhp[3 * HH * DD + i2] + bq[i2]) * 0.125f;
    float a = q1 * bk[i1] + q2 * bk[i2];
    #pragma unroll
    for (int o = 16; o; o >>= 1) a += __shfl_xor_sync(~0u, a, o);
    if (lane == 0) g_sbias[h] = a;
}

// ================= fused (mma.sync): scores MMA -> exp -> y^T MMA =================
// 512 threads, 68.7 KB smem -> 3 blocks/SM (48 warps). 8 c-slices of 96.
// Phase 1: warps 0-7 own 16-row m-tiles, dual head-half accumulators.
// Phase 2: Y^T[96c,16h] = X^T . P^T per slice; c-tiles 0-5 on warps 0-5.
__global__ __launch_bounds__(512, 3) void k_fused(const float* __restrict__ x) {
    extern __shared__ __align__(16) char smem[];
    const uint32_t sb = smem_u32(smem);
    int t = threadIdx.x, w = t >> 5, lane = t & 31;
    int ch = blockIdx.x, b = blockIdx.y;
    int s0 = ch * SCHUNK;
    const float* xb = x + (size_t)b * SS * CC;
    int gid = lane >> 2, tig = lane & 3;

    if (t < 16) {
        ((float*)(smem + OFF_ZSH))[t] = 0.f;
        ((float*)(smem + OFF_SBS))[t] = (t < HH) ? g_sbias[t] : 0.f;
    }

    float d0[4] = {0.f, 0.f, 0.f, 0.f}, d1[4] = {0.f, 0.f, 0.f, 0.f};
    // phase-1 A: x rows 16w.., non-trans x4
    uint32_t xA  = sb + OFF_XH + (16 * (w & 7) + (lane & 15)) * XSTR + (lane >> 4) * 16;
    uint32_t xAl = xA + (OFF_XL - OFF_XH);
    // phase-1 B fused hi+lo: lanes 0-15 hi, 16-31 lo
    uint32_t wkB0 = sb + OFF_WKH + (lane & 7) * XSTR + ((lane >> 3) & 1) * 16
                  + ((lane >> 4) & 1) * (OFF_WKL - OFF_WKH);
    uint32_t wkB1 = wkB0 + 8 * XSTR;

    // ===== phase 1: scores over 8 c-slices of 96 =====
    for (int sl = 0; sl < NSLICE; sl++) {
        __syncthreads();
        const float* xs = xb + (size_t)s0 * CC + sl * 96;
        #pragma unroll
        for (int j = 0; j < 6; j++) {               // 3072 float4 items / 512
            int i = t + j * 512;
            int r = i / 24, c4 = i - r * 24;
            float4 v = *(const float4*)(xs + (size_t)r * CC + c4 * 4);
            uint32_t h0 = pbf2(v.x, v.y), h1 = pbf2(v.z, v.w);
            float l0 = v.x - __uint_as_float(h0 << 16);
            float l1 = v.y - __uint_as_float(h0 & 0xffff0000u);
            float l2 = v.z - __uint_as_float(h1 << 16);
            float l3 = v.w - __uint_as_float(h1 & 0xffff0000u);
            *(uint2*)(smem + OFF_XH + r * XSTR + c4 * 8) = make_uint2(h0, h1);
            *(uint2*)(smem + OFF_XL + r * XSTR + c4 * 8) = make_uint2(pbf2(l0, l1), pbf2(l2, l3));
        }
        if (t < 384) {   // wk slice: 16 rows x 24 uint2
            int h = t / 24, c4 = t - h * 24;
            *(uint2*)(smem + OFF_WKH + h * XSTR + c4 * 8) =
                *(const uint2*)(g_wkh + h * CC + sl * 96 + c4 * 4);
            *(uint2*)(smem + OFF_WKL + h * XSTR + c4 * 8) =
                *(const uint2*)(g_wkl + h * CC + sl * 96 + c4 * 4);
        }
        __syncthreads();
        if (w < 8) {
            #pragma unroll
            for (int kk = 0; kk < 6; kk++) {
                uint32_t ah[4], al[4], b0[4], b1[4];
                ldm_x4(ah, xA + kk * 32);
                ldm_x4(al, xAl + kk * 32);
                ldm_x4(b0, wkB0 + kk * 32);
                ldm_x4(b1, wkB1 + kk * 32);
                mma16816(d0, ah, b0);
                mma16816(d0, ah, b0 + 2);
                mma16816(d0, al, b0);
                mma16816(d1, ah, b1);
                mma16816(d1, ah, b1 + 2);
                mma16816(d1, al, b1);
            }
        }
    }

    // ===== exp + P (bf16 hi/lo, [16h][128s] stride 272B) + z =====
    if (w < 8) {
        const float* sbs = (const float*)(smem + OFF_SBS);
        int h0 = 2 * tig, r0 = 16 * w + gid;
        float e[8];
        e[0] = __expf(d0[0] + sbs[h0]);     e[1] = __expf(d0[1] + sbs[h0 + 1]);
        e[2] = __expf(d0[2] + sbs[h0]);     e[3] = __expf(d0[3] + sbs[h0 + 1]);
        e[4] = __expf(d1[0] + sbs[h0 + 8]); e[5] = __expf(d1[1] + sbs[h0 + 9]);
        e[6] = __expf(d1[2] + sbs[h0 + 8]); e[7] = __expf(d1[3] + sbs[h0 + 9]);
        #pragma unroll
        for (int k = 0; k < 8; k++) {
            int hh = (k < 4 ? h0 : h0 + 8) + (k & 1);
            int ss = r0 + ((k >> 1) & 1) * 8;
            __nv_bfloat16 hbf = __float2bfloat16(e[k]);
            float lo = e[k] - __bfloat162float(hbf);
            *(__nv_bfloat16*)(smem + OFF_PH + hh * PSTR + ss * 2) = hbf;
            *(__nv_bfloat16*)(smem + OFF_PL + hh * PSTR + ss * 2) = __float2bfloat16(lo);
        }
        float v0 = e[0] + e[2], v1 = e[1] + e[3], v2 = e[4] + e[6], v3 = e[5] + e[7];
        #pragma unroll
        for (int o = 4; o < 32; o <<= 1) {
            v0 += __shfl_xor_sync(~0u, v0, o);
            v1 += __shfl_xor_sync(~0u, v1, o);
            v2 += __shfl_xor_sync(~0u, v2, o);
            v3 += __shfl_xor_sync(~0u, v3, o);
        }
        if (lane < 4) {
            float* zsh = (float*)(smem + OFF_ZSH);
            atomicAdd(&zsh[2 * lane],     v0);
            atomicAdd(&zsh[2 * lane + 1], v1);
            atomicAdd(&zsh[2 * lane + 8], v2);
            atomicAdd(&zsh[2 * lane + 9], v3);
        }
    }
    __syncthreads();
    if (t < HH) g_z[(b * NCHUNK + ch) * HH + t] = ((float*)(smem + OFF_ZSH))[t];

    // ===== phase 2: Y^T[96c,16h] = X^T . P^T, REVERSE slices for L2 recency =====
    uint32_t xT  = sb + OFF_XH + ((lane & 7) + ((lane >> 4) & 1) * 8) * XSTR
                 + (16 * (w & 7) + ((lane >> 3) & 1) * 8) * 2;
    uint32_t xTl = xT + (OFF_XL - OFF_XH);
    uint32_t pB0 = sb + OFF_PH + (lane & 7) * PSTR + ((lane >> 3) & 1) * 16
                 + ((lane >> 4) & 1) * (OFF_PL - OFF_PH);
    uint32_t pB1 = pB0 + 8 * PSTR;
    float* ypb = g_ypart + (size_t)(b * NCHUNK + ch) * (HH * CC);

    for (int sl = NSLICE - 1; sl >= 0; sl--) {
        __syncthreads();
        const float* xs = xb + (size_t)s0 * CC + sl * 96;
        #pragma unroll
        for (int j = 0; j < 6; j++) {
            int i = t + j * 512;
            int r = i / 24, c4 = i - r * 24;
            float4 v = *(const float4*)(xs + (size_t)r * CC + c4 * 4);
            uint32_t h0 = pbf2(v.x, v.y), h1 = pbf2(v.z, v.w);
            float l0 = v.x - __uint_as_float(h0 << 16);
            float l1 = v.y - __uint_as_float(h0 & 0xffff0000u);
            float l2 = v.z - __uint_as_float(h1 << 16);
            float l3 = v.w - __uint_as_float(h1 & 0xffff0000u);
            *(uint2*)(smem + OFF_XH + r * XSTR + c4 * 8) = make_uint2(h0, h1);
            *(uint2*)(smem + OFF_XL + r * XSTR + c4 * 8) = make_uint2(pbf2(l0, l1), pbf2(l2, l3));
        }
        __syncthreads();

        if (w < 6) {            // 6 c-tiles of 16
            float dA[4] = {0.f, 0.f, 0.f, 0.f}, dB[4] = {0.f, 0.f, 0.f, 0.f};
            #pragma unroll
            for (int kk = 0; kk < 8; kk++) {
                uint32_t ah[4], al[4], b0[4], b1[4];
                ldm_x4t(ah, xT + kk * 16 * XSTR);
                ldm_x4t(al, xTl + kk * 16 * XSTR);
                ldm_x4(b0, pB0 + kk * 32);
                ldm_x4(b1, pB1 + kk * 32);
                mma16816(dA, ah, b0);
                mma16816(dA, ah, b0 + 2);
                mma16816(dA, al, b0);
                mma16816(dB, ah, b1);
                mma16816(dB, ah, b1 + 2);
                mma16816(dB, al, b1);
            }
            int c0 = sl * 96 + 16 * w;
            int h0 = 2 * tig;
            ypb[(size_t)h0 * CC + c0 + gid]           = dA[0];
            ypb[(size_t)(h0 + 1) * CC + c0 + gid]     = dA[1];
            ypb[(size_t)h0 * CC + c0 + gid + 8]       = dA[2];
            ypb[(size_t)(h0 + 1) * CC + c0 + gid + 8] = dA[3];
            if (h0 + 8 < HH) {
                ypb[(size_t)(h0 + 8) * CC + c0 + gid]     = dB[0];
                ypb[(size_t)(h0 + 8) * CC + c0 + gid + 8] = dB[2];
            }
            if (h0 + 9 < HH) {
                ypb[(size_t)(h0 + 9) * CC + c0 + gid]     = dB[1];
                ypb[(size_t)(h0 + 9) * CC + c0 + gid + 8] = dB[3];
            }
        }
    }
}

// ================= combine + ctx (FROZEN round-7 version) =================
__global__ __launch_bounds__(256) void k_combctx(const float* __restrict__ Wv,
                                                 const float* __restrict__ bv) {
    int b = blockIdx.x, h = blockIdx.y, t = threadIdx.x;
    __shared__ float ys[CC];
    __shared__ float red[4][DD];
    __shared__ float invZ_s;

    if (t < 32) {
        float z = 0.f;
        for (int c2 = t; c2 < NCHUNK; c2 += 32) z += g_z[(b * NCHUNK + c2) * HH + h];
        #pragma unroll
        for (int o = 16; o; o >>= 1) z += __shfl_xor_sync(~0u, z, o);
        if (t == 0) invZ_s = 1.f / z;
    }
    __syncthreads();
    float invZ = invZ_s;

    #pragma unroll
    for (int i = 0; i < 3; i++) {
        int c = t + 256 * i;
        const float* base = g_ypart + (size_t)b * NCHUNK * HH * CC + h * CC + c;
        float a0 = 0.f, a1 = 0.f, a2 = 0.f, a3 = 0.f;
        #pragma unroll 4
        for (int chn = 0; chn < NCHUNK - 3; chn += 4) {
            a0 += base[(size_t)chn * HH * CC];
            a1 += base[(size_t)(chn + 1) * HH * CC];
            a2 += base[(size_t)(chn + 2) * HH * CC];
            a3 += base[(size_t)(chn + 3) * HH * CC];
        }
        for (int chn = NCHUNK & ~3; chn < NCHUNK; chn++)
            a0 += base[(size_t)chn * HH * CC];
        ys[c] = ((a0 + a1) + (a2 + a3)) * invZ;
    }
    __syncthreads();

    int d = t & 63, part = t >> 6;
    const float* wp = Wv + h * DD + d;
    float a0 = 0.f, a1 = 0.f;
    #pragma unroll 8
    for (int c = part; c < CC; c += 8) {
        a0 = fmaf(ys[c],     wp[(size_t)c * CC],       a0);
        a1 = fmaf(ys[c + 4], wp[(size_t)(c + 4) * CC], a1);
    }
    red[part][d] = a0 + a1;
    __syncthreads();
    if (t < DD)
        g_ctx[b * CC + h * DD + t] =
            red[0][t] + red[1][t] + red[2][t] + red[3][t] + bv[h * DD + t];
}

// ================= out (FROZEN round-7 version) =================
__global__ __launch_bounds__(192) void k_out(const float* __restrict__ Wo,
                                             const float* __restrict__ bo,
                                             float* __restrict__ out) {
    int b = blockIdx.x, part = blockIdx.y, t = threadIdx.x;
    __shared__ float cs[CC];
    for (int i = t; i < CC; i += 192) cs[i] = g_ctx[b * CC + i];
    __syncthreads();
    int cp = part * 192 + t;
    const float* wp = Wo + cp;
    float a0 = 0.f, a1 = 0.f, a2 = 0.f, a3 = 0.f;
    #pragma unroll 8
    for (int o = 0; o < CC; o += 4) {
        a0 = fmaf(cs[o],     wp[(size_t)o * CC],       a0);
        a1 = fmaf(cs[o + 1], wp[(size_t)(o + 1) * CC], a1);
        a2 = fmaf(cs[o + 2], wp[(size_t)(o + 2) * CC], a2);
        a3 = fmaf(cs[o + 3], wp[(size_t)(o + 3) * CC], a3);
    }
    out[(size_t)b * CC + cp] = (a0 + a1) + (a2 + a3) + bo[cp];
}

extern "C" void kernel_launch(void* const* d_in, const int* in_sizes, int n_in,
                              void* d_out, int out_size) {
    const float* x     = (const float*)d_in[0];
    const float* probe = (const float*)d_in[1];
    const float* Wq    = (const float*)d_in[2];
    const float* bq    = (const float*)d_in[3];
    const float* Wk    = (const float*)d_in[4];
    const float* bk    = (const float*)d_in[5];
    const float* Wv    = (const float*)d_in[6];
    const float* bv    = (const float*)d_in[7];
    const float* Wo    = (const float*)d_in[8];
    const float* bo    = (const float*)d_in[9];
    float* out = (float*)d_out;

    cudaFuncSetAttribute(k_fused, cudaFuncAttributeMaxDynamicSharedMemorySize, SMEM_TOTAL);

    k_prep_qh<<<dim3(HH, 4), 256>>>(probe, Wq);             // #1
    k_prep_wk<<<dim3(HH, 8), 256>>>(Wk, bq);                // #2
    k_prep_sb<<<1, 384>>>(bq, bk);                          // #3
    k_fused<<<dim3(NCHUNK, BB), 512, SMEM_TOTAL>>>(x);      // #4  <- profiled slot
    k_combctx<<<dim3(BB, HH), 256>>>(Wv, bv);               // #5
    k_out<<<dim3(BB, 4), 192>>>(Wo, bo, out);               // #6
}